// round 12
// baseline (speedup 1.0000x reference)
#include <cuda_runtime.h>

// ---------------- scratch (device globals; no allocations allowed) ----------
__device__ float g_t1 [8 * 32 * 128 * 128];      // project1 conv1 out (ReLU)
__device__ float g_g  [8 * 32 * 128 * 128];      // guidance conv1 out (ReLU)
__device__ float g_xp [8 * 16 * 128 * 128];      // project1 conv2 out (ReLU)
__device__ float g_wts[8 * 16 * 9 * 128 * 128];  // softmax weights (n, pq, k, hw)
__device__ float g_up [8 * 16 * 512 * 512];      // upsampled NCHW
__device__ float g_mid[8 *  8 * 512 * 512];      // project2 conv1 out (ReLU)

// ---------------- tf32 helpers ----------------------------------------------
__device__ __forceinline__ unsigned tf32_rna(float x) {
    unsigned r; asm("cvt.rna.tf32.f32 %0, %1;" : "=r"(r) : "f"(x)); return r;
}
__device__ __forceinline__ void mma_tf32(float& c0, float& c1, float& c2, float& c3,
                                         unsigned a0, unsigned a1, unsigned a2, unsigned a3,
                                         unsigned b0, unsigned b1) {
    asm volatile("mma.sync.aligned.m16n8k8.row.col.f32.tf32.tf32.f32 "
                 "{%0,%1,%2,%3}, {%4,%5,%6,%7}, {%8,%9}, {%0,%1,%2,%3};"
                 : "+f"(c0), "+f"(c1), "+f"(c2), "+f"(c3)
                 : "r"(a0), "r"(a1), "r"(a2), "r"(a3), "r"(b0), "r"(b1));
}

// ============ generic k3 conv via tf32 MMA on 128x128 images =================
// Tile: 4 rows x 64 cols. CIN processed in CIN/8 chunks of 8.
// CT = COUT/8 output-channel groups. Weights pre-split tf32 hi/lo in smem.
template <int CIN, int COUT, bool RELU>
__global__ __launch_bounds__(256)
void conv_k3_mma(const float* __restrict__ in,
                 const float* __restrict__ wgt,
                 const float* __restrict__ bias,
                 float* __restrict__ out)
{
    constexpr int HW = 128;
    constexpr int CP = 68;
    constexpr int PLANE = 6 * CP;
    constexpr int NCH = CIN / 8;
    constexpr int CT  = COUT / 8;
    constexpr int WSZ = COUT * 8 * 9;      // weights per cin-chunk
    extern __shared__ unsigned sm[];
    unsigned* s_hi = sm;                   // [8][6][CP]
    unsigned* s_lo = s_hi + 8 * PLANE;
    unsigned* s_wh = s_lo + 8 * PLANE;     // [COUT][8 ci][9 tap]
    unsigned* s_wl = s_wh + WSZ;

    const int n  = blockIdx.z;
    const int h0 = blockIdx.y * 4;
    const int w0 = blockIdx.x * 64;
    const int tid = threadIdx.x;
    const int warp = tid >> 5, lane = tid & 31;
    const int g = lane >> 2, t = lane & 3;

    float acc[CT][2][4];
#pragma unroll
    for (int ct = 0; ct < CT; ct++) {
        float b0 = bias[ct * 8 + 2 * t], b1 = bias[ct * 8 + 2 * t + 1];
#pragma unroll
        for (int t2 = 0; t2 < 2; t2++) {
            acc[ct][t2][0] = b0; acc[ct][t2][1] = b1;
            acc[ct][t2][2] = b0; acc[ct][t2][3] = b1;
        }
    }

#pragma unroll 1
    for (int chunk = 0; chunk < NCH; chunk++) {
        __syncthreads();
        for (int i = tid; i < 8 * 6 * 66; i += 256) {
            int ci = i / 396, rem = i % 396;
            int r = rem / 66, c = rem % 66;
            int gh = h0 + r - 1, gw = w0 + c - 1;
            float v = 0.f;
            if (gh >= 0 && gh < HW && gw >= 0 && gw < HW)
                v = in[((n * CIN + chunk * 8 + ci) * HW + gh) * HW + gw];
            unsigned hi = tf32_rna(v);
            int a = ci * PLANE + r * CP + c;
            s_hi[a] = hi;
            s_lo[a] = tf32_rna(v - __uint_as_float(hi));
        }
        for (int i = tid; i < WSZ; i += 256) {
            int co = i / 72, rem = i % 72;
            float raw = wgt[co * (CIN * 9) + chunk * 72 + rem];
            unsigned hi = tf32_rna(raw);
            s_wh[i] = hi;
            s_wl[i] = tf32_rna(raw - __uint_as_float(hi));
        }
        __syncthreads();

#pragma unroll
        for (int dh = 0; dh < 3; dh++) {
#pragma unroll
            for (int dw = 0; dw < 3; dw++) {
                const int tap = dh * 3 + dw;
                unsigned A[2][8];
#pragma unroll
                for (int t2 = 0; t2 < 2; t2++) {
                    const int id = warp + 8 * t2;
                    const int r = id >> 2, cs = id & 3;
                    const int base = t * PLANE + (r + dh) * CP + cs * 16 + g + dw;
                    A[t2][0] = s_hi[base];             A[t2][1] = s_hi[base + 8];
                    A[t2][2] = s_hi[base + 4 * PLANE]; A[t2][3] = s_hi[base + 8 + 4 * PLANE];
                    A[t2][4] = s_lo[base];             A[t2][5] = s_lo[base + 8];
                    A[t2][6] = s_lo[base + 4 * PLANE]; A[t2][7] = s_lo[base + 8 + 4 * PLANE];
                }
#pragma unroll
                for (int ct = 0; ct < CT; ct++) {
                    const int wb = (ct * 8 + g) * 72 + tap;
                    unsigned bh0 = s_wh[wb + t * 9], bh1 = s_wh[wb + (t + 4) * 9];
                    unsigned bl0 = s_wl[wb + t * 9], bl1 = s_wl[wb + (t + 4) * 9];
#pragma unroll
                    for (int t2 = 0; t2 < 2; t2++) {
                        mma_tf32(acc[ct][t2][0], acc[ct][t2][1], acc[ct][t2][2], acc[ct][t2][3],
                                 A[t2][0], A[t2][1], A[t2][2], A[t2][3], bh0, bh1);
                        mma_tf32(acc[ct][t2][0], acc[ct][t2][1], acc[ct][t2][2], acc[ct][t2][3],
                                 A[t2][0], A[t2][1], A[t2][2], A[t2][3], bl0, bl1);
                        mma_tf32(acc[ct][t2][0], acc[ct][t2][1], acc[ct][t2][2], acc[ct][t2][3],
                                 A[t2][4], A[t2][5], A[t2][6], A[t2][7], bh0, bh1);
                    }
                }
            }
        }
    }

#pragma unroll
    for (int ct = 0; ct < CT; ct++) {
#pragma unroll
        for (int t2 = 0; t2 < 2; t2++) {
            const int id = warp + 8 * t2;
            const int r = id >> 2, cs = id & 3;
            const int h = h0 + r, w = w0 + cs * 16 + g;
            const int co = ct * 8 + 2 * t;
            const int ob = ((n * COUT + co) * HW + h) * HW + w;
            float v0 = acc[ct][t2][0], v1 = acc[ct][t2][1];
            float v2 = acc[ct][t2][2], v3 = acc[ct][t2][3];
            if (RELU) { v0 = fmaxf(v0, 0.f); v1 = fmaxf(v1, 0.f);
                        v2 = fmaxf(v2, 0.f); v3 = fmaxf(v3, 0.f); }
            out[ob]               = v0;
            out[ob + HW * HW]     = v1;
            out[ob + 8]           = v2;
            out[ob + HW * HW + 8] = v3;
        }
    }
}

// ============ stage-1 dual 64->32 k3 ReLU via tf32 MMA (128x128) =============
__global__ __launch_bounds__(256)
void conv_s1_mma(const float* __restrict__ in,
                 const float* __restrict__ wA, const float* __restrict__ bA,
                 float* __restrict__ outA,
                 const float* __restrict__ wB, const float* __restrict__ bB,
                 float* __restrict__ outB)
{
    constexpr int HW = 128;
    constexpr int CP = 68;
    constexpr int PLANE = 6 * CP;
    extern __shared__ unsigned sm[];
    unsigned* s_hi = sm;                   // [8][6][CP]
    unsigned* s_lo = s_hi + 8 * PLANE;
    unsigned* s_wh = s_lo + 8 * PLANE;     // [32 co][8 ci][9 tap]
    unsigned* s_wl = s_wh + 2304;

    const int which = blockIdx.z & 1;
    const int n  = blockIdx.z >> 1;
    const float* wgt  = which ? wB : wA;
    const float* bias = which ? bB : bA;
    float*       out  = which ? outB : outA;

    const int h0 = blockIdx.y * 4;
    const int w0 = blockIdx.x * 64;
    const int tid = threadIdx.x;
    const int warp = tid >> 5, lane = tid & 31;
    const int g = lane >> 2, t = lane & 3;

    float acc[4][2][4];
#pragma unroll
    for (int ct = 0; ct < 4; ct++) {
        float b0 = bias[ct * 8 + 2 * t], b1 = bias[ct * 8 + 2 * t + 1];
#pragma unroll
        for (int t2 = 0; t2 < 2; t2++) {
            acc[ct][t2][0] = b0; acc[ct][t2][1] = b1;
            acc[ct][t2][2] = b0; acc[ct][t2][3] = b1;
        }
    }

#pragma unroll 1
    for (int chunk = 0; chunk < 8; chunk++) {
        __syncthreads();
        for (int i = tid; i < 8 * 6 * 66; i += 256) {
            int ci = i / 396, rem = i % 396;
            int r = rem / 66, c = rem % 66;
            int gh = h0 + r - 1, gw = w0 + c - 1;
            float v = 0.f;
            if (gh >= 0 && gh < HW && gw >= 0 && gw < HW)
                v = in[((n * 64 + chunk * 8 + ci) * HW + gh) * HW + gw];
            unsigned hi = tf32_rna(v);
            int a = ci * PLANE + r * CP + c;
            s_hi[a] = hi;
            s_lo[a] = tf32_rna(v - __uint_as_float(hi));
        }
        for (int i = tid; i < 2304; i += 256) {
            int co = i / 72, rem = i % 72;
            float raw = wgt[co * 576 + chunk * 72 + rem];
            unsigned hi = tf32_rna(raw);
            s_wh[i] = hi;
            s_wl[i] = tf32_rna(raw - __uint_as_float(hi));
        }
        __syncthreads();

#pragma unroll
        for (int dh = 0; dh < 3; dh++) {
#pragma unroll
            for (int dw = 0; dw < 3; dw++) {
                const int tap = dh * 3 + dw;
                unsigned A[2][8];
#pragma unroll
                for (int t2 = 0; t2 < 2; t2++) {
                    const int id = warp + 8 * t2;
                    const int r = id >> 2, cs = id & 3;
                    const int base = t * PLANE + (r + dh) * CP + cs * 16 + g + dw;
                    A[t2][0] = s_hi[base];             A[t2][1] = s_hi[base + 8];
                    A[t2][2] = s_hi[base + 4 * PLANE]; A[t2][3] = s_hi[base + 8 + 4 * PLANE];
                    A[t2][4] = s_lo[base];             A[t2][5] = s_lo[base + 8];
                    A[t2][6] = s_lo[base + 4 * PLANE]; A[t2][7] = s_lo[base + 8 + 4 * PLANE];
                }
#pragma unroll
                for (int ct = 0; ct < 4; ct++) {
                    const int wb = (ct * 8 + g) * 72 + tap;
                    unsigned bh0 = s_wh[wb + t * 9], bh1 = s_wh[wb + (t + 4) * 9];
                    unsigned bl0 = s_wl[wb + t * 9], bl1 = s_wl[wb + (t + 4) * 9];
#pragma unroll
                    for (int t2 = 0; t2 < 2; t2++) {
                        mma_tf32(acc[ct][t2][0], acc[ct][t2][1], acc[ct][t2][2], acc[ct][t2][3],
                                 A[t2][0], A[t2][1], A[t2][2], A[t2][3], bh0, bh1);
                        mma_tf32(acc[ct][t2][0], acc[ct][t2][1], acc[ct][t2][2], acc[ct][t2][3],
                                 A[t2][0], A[t2][1], A[t2][2], A[t2][3], bl0, bl1);
                        mma_tf32(acc[ct][t2][0], acc[ct][t2][1], acc[ct][t2][2], acc[ct][t2][3],
                                 A[t2][4], A[t2][5], A[t2][6], A[t2][7], bh0, bh1);
                    }
                }
            }
        }
    }

#pragma unroll
    for (int ct = 0; ct < 4; ct++) {
#pragma unroll
        for (int t2 = 0; t2 < 2; t2++) {
            const int id = warp + 8 * t2;
            const int r = id >> 2, cs = id & 3;
            const int h = h0 + r, w = w0 + cs * 16 + g;
            const int co = ct * 8 + 2 * t;
            const int ob = ((n * 32 + co) * HW + h) * HW + w;
            out[ob]               = fmaxf(acc[ct][t2][0], 0.f);
            out[ob + HW * HW]     = fmaxf(acc[ct][t2][1], 0.f);
            out[ob + 8]           = fmaxf(acc[ct][t2][2], 0.f);
            out[ob + HW * HW + 8] = fmaxf(acc[ct][t2][3], 0.f);
        }
    }
}

// ------------- guidance 1x1 conv (32->144) + per-(p,q) softmax over 9 -------
__global__ void gw_softmax_kernel(const float* __restrict__ g,
                                  const float* __restrict__ w2,
                                  const float* __restrict__ b2,
                                  float* __restrict__ wts)
{
    constexpr int HW = 128 * 128;
    __shared__ float s_w[144 * 32];
    __shared__ float s_b[144];
    for (int i = threadIdx.x; i < 144 * 32; i += 256) s_w[i] = w2[i];
    for (int i = threadIdx.x; i < 144;      i += 256) s_b[i] = b2[i];
    __syncthreads();

    const int pix = blockIdx.x * 256 + threadIdx.x;
    const int n = pix / HW, hw = pix % HW;

    float gv[32];
#pragma unroll
    for (int c = 0; c < 32; c++) gv[c] = g[(n * 32 + c) * HW + hw];

    for (int pq = 0; pq < 16; pq++) {
        float v[9];
#pragma unroll
        for (int k = 0; k < 9; k++) {
            const int ch = k * 16 + pq;
            float acc = s_b[ch];
            const float* wp = &s_w[ch * 32];
#pragma unroll
            for (int c = 0; c < 32; c++) acc = fmaf(gv[c], wp[c], acc);
            v[k] = acc;
        }
        float m = v[0];
#pragma unroll
        for (int k = 1; k < 9; k++) m = fmaxf(m, v[k]);
        float s = 0.f;
#pragma unroll
        for (int k = 0; k < 9; k++) { v[k] = __expf(v[k] - m); s += v[k]; }
        const float inv = 1.f / s;
#pragma unroll
        for (int k = 0; k < 9; k++)
            wts[((n * 16 + pq) * 9 + k) * HW + hw] = v[k] * inv;
    }
}

// ------------- convex upsample + pixel shuffle ------------------------------
__global__ void upsample_kernel(const float* __restrict__ xp,
                                const float* __restrict__ wts,
                                float* __restrict__ up)
{
    constexpr int H = 128, W = 128, HW = H * W;
    __shared__ float s_xp[16][3][18];

    const int n = blockIdx.z, h = blockIdx.y, wtile = blockIdx.x * 16;
    const int tid = threadIdx.y * 64 + threadIdx.x;

    for (int i = tid; i < 16 * 3 * 18; i += 256) {
        int c = i / 54, rem = i % 54, r = rem / 18, col = rem % 18;
        int gh = h + r - 1, gw = wtile + col - 1;
        float v = 0.f;
        if (gh >= 0 && gh < H && gw >= 0 && gw < W)
            v = xp[(n * 16 + c) * HW + gh * W + gw];
        s_xp[c][r][col] = v;
    }
    __syncthreads();

    const int p  = threadIdx.y;
    const int q  = threadIdx.x & 3;
    const int wl = threadIdx.x >> 2;
    const int pq = p * 4 + q;
    const int hw = h * W + wtile + wl;

    float wt[9];
#pragma unroll
    for (int k = 0; k < 9; k++) wt[k] = wts[((n * 16 + pq) * 9 + k) * HW + hw];

    const int h_hi = h * 4 + p;
    const int w_hi = (wtile + wl) * 4 + q;
#pragma unroll
    for (int c = 0; c < 16; c++) {
        float acc = 0.f;
#pragma unroll
        for (int i = 0; i < 3; i++)
#pragma unroll
            for (int j = 0; j < 3; j++)
                acc = fmaf(wt[i * 3 + j], s_xp[c][i][wl + j], acc);
        up[((n * 16 + c) * 512 + h_hi) * 512 + w_hi] = acc;
    }
}

// ================= project2 conv1: 16->8, k5, ReLU, 512x512, tf32 MMA ========
__global__ __launch_bounds__(256)
void conv_p2a_mma(const float* __restrict__ in,
                  const float* __restrict__ wgt,
                  const float* __restrict__ bias,
                  float* __restrict__ out)
{
    constexpr int HW = 512;
    constexpr int CP = 69;
    constexpr int PLANE = 8 * CP;
    extern __shared__ unsigned sm[];
    unsigned* s_hi = sm;                    // 16*PLANE
    unsigned* s_lo = s_hi + 16 * PLANE;
    unsigned* s_wh = s_lo + 16 * PLANE;     // 3200
    unsigned* s_wl = s_wh + 3200;           // 3200
    float*    s_b  = (float*)(s_wl + 3200);

    const int n  = blockIdx.z;
    const int h0 = blockIdx.y * 4;
    const int w0 = blockIdx.x * 64;
    const int tid = threadIdx.x;

    for (int i = tid; i < 16 * 8 * 68; i += 256) {
        int cin = i / (8 * 68), rem = i % (8 * 68);
        int r = rem / 68, c = rem % 68;
        int gh = h0 + r - 2, gw = w0 + c - 2;
        float v = 0.f;
        if (gh >= 0 && gh < HW && gw >= 0 && gw < HW)
            v = in[((n * 16 + cin) * HW + gh) * HW + gw];
        unsigned hi = tf32_rna(v);
        float lo = v - __uint_as_float(hi);
        int a = cin * PLANE + r * CP + c;
        s_hi[a] = hi;
        s_lo[a] = tf32_rna(lo);
    }
    for (int i = tid; i < 3200; i += 256) {
        float raw = wgt[i];
        unsigned hi = tf32_rna(raw);
        s_wh[i] = hi;
        s_wl[i] = tf32_rna(raw - __uint_as_float(hi));
    }
    if (tid < 8) s_b[tid] = bias[tid];
    __syncthreads();

    const int warp = tid >> 5, lane = tid & 31;
    const int g = lane >> 2, t = lane & 3;

    float c[2][4];
#pragma unroll
    for (int t2 = 0; t2 < 2; t2++) {
        c[t2][0] = s_b[2 * t];     c[t2][1] = s_b[2 * t + 1];
        c[t2][2] = c[t2][0];       c[t2][3] = c[t2][1];
    }

#pragma unroll
    for (int dh = 0; dh < 5; dh++) {
#pragma unroll
        for (int dw = 0; dw < 5; dw++) {
            const int tap = dh * 5 + dw;
#pragma unroll
            for (int ch = 0; ch < 2; ch++) {
                const int wb0 = g * 400 + (ch * 8 + t) * 25 + tap;
                const int wb1 = g * 400 + (ch * 8 + t + 4) * 25 + tap;
                unsigned bh0 = s_wh[wb0], bh1 = s_wh[wb1];
                unsigned bl0 = s_wl[wb0], bl1 = s_wl[wb1];
#pragma unroll
                for (int t2 = 0; t2 < 2; t2++) {
                    const int id = warp + 8 * t2;
                    const int r = id >> 2, cs = id & 3;
                    const int base = (ch * 8 + t) * PLANE + (r + dh) * CP + cs * 16 + g + dw;
                    unsigned a0 = s_hi[base],             a1 = s_hi[base + 8];
                    unsigned a2 = s_hi[base + 4 * PLANE], a3 = s_hi[base + 4 * PLANE + 8];
                    unsigned l0 = s_lo[base],             l1 = s_lo[base + 8];
                    unsigned l2 = s_lo[base + 4 * PLANE], l3 = s_lo[base + 4 * PLANE + 8];
                    mma_tf32(c[t2][0], c[t2][1], c[t2][2], c[t2][3], a0, a1, a2, a3, bh0, bh1);
                    mma_tf32(c[t2][0], c[t2][1], c[t2][2], c[t2][3], a0, a1, a2, a3, bl0, bl1);
                    mma_tf32(c[t2][0], c[t2][1], c[t2][2], c[t2][3], l0, l1, l2, l3, bh0, bh1);
                }
            }
        }
    }

#pragma unroll
    for (int t2 = 0; t2 < 2; t2++) {
        const int id = warp + 8 * t2;
        const int r = id >> 2, cs = id & 3;
        const int h = h0 + r, w = w0 + cs * 16 + g;
        const int ob = ((n * 8 + 2 * t) * HW + h) * HW + w;
        out[ob]                = fmaxf(c[t2][0], 0.f);
        out[ob + HW * HW]      = fmaxf(c[t2][1], 0.f);
        out[ob + 8]            = fmaxf(c[t2][2], 0.f);
        out[ob + HW * HW + 8]  = fmaxf(c[t2][3], 0.f);
    }
}

// ================= project2 conv2: 8->64, k3, 512x512, tf32 MMA ==============
__global__ __launch_bounds__(256)
void conv_p2b_mma(const float* __restrict__ in,
                  const float* __restrict__ wgt,
                  const float* __restrict__ bias,
                  float* __restrict__ out)
{
    constexpr int HW = 512;
    constexpr int CP = 68;
    constexpr int PLANE = 6 * CP;
    extern __shared__ unsigned sm[];
    unsigned* s_hi = sm;                    // 8*PLANE
    unsigned* s_lo = s_hi + 8 * PLANE;
    unsigned* s_wh = s_lo + 8 * PLANE;      // 4608
    unsigned* s_wl = s_wh + 4608;           // 4608
    float*    s_b  = (float*)(s_wl + 4608); // 64

    const int n  = blockIdx.z;
    const int h0 = blockIdx.y * 4;
    const int w0 = blockIdx.x * 64;
    const int tid = threadIdx.x;

    for (int i = tid; i < 8 * 6 * 66; i += 256) {
        int cin = i / (6 * 66), rem = i % (6 * 66);
        int r = rem / 66, c = rem % 66;
        int gh = h0 + r - 1, gw = w0 + c - 1;
        float v = 0.f;
        if (gh >= 0 && gh < HW && gw >= 0 && gw < HW)
            v = in[((n * 8 + cin) * HW + gh) * HW + gw];
        unsigned hi = tf32_rna(v);
        float lo = v - __uint_as_float(hi);
        int a = cin * PLANE + r * CP + c;
        s_hi[a] = hi;
        s_lo[a] = tf32_rna(lo);
    }
    for (int i = tid; i < 4608; i += 256) {
        float raw = wgt[i];
        unsigned hi = tf32_rna(raw);
        s_wh[i] = hi;
        s_wl[i] = tf32_rna(raw - __uint_as_float(hi));
    }
    if (tid < 64) s_b[tid] = bias[tid];
    __syncthreads();

    const int warp = tid >> 5, lane = tid & 31;
    const int g = lane >> 2, t = lane & 3;

#pragma unroll 1
    for (int half = 0; half < 2; half++) {
        float acc[4][2][4];
#pragma unroll
        for (int c4 = 0; c4 < 4; c4++) {
            const int ct = half * 4 + c4;
            float b0 = s_b[ct * 8 + 2 * t], b1 = s_b[ct * 8 + 2 * t + 1];
#pragma unroll
            for (int t2 = 0; t2 < 2; t2++) {
                acc[c4][t2][0] = b0; acc[c4][t2][1] = b1;
                acc[c4][t2][2] = b0; acc[c4][t2][3] = b1;
            }
        }

#pragma unroll
        for (int dh = 0; dh < 3; dh++) {
#pragma unroll
            for (int dw = 0; dw < 3; dw++) {
                const int tap = dh * 3 + dw;
                unsigned A[2][8];
#pragma unroll
                for (int t2 = 0; t2 < 2; t2++) {
                    const int id = warp + 8 * t2;
                    const int r = id >> 2, cs = id & 3;
                    const int base = t * PLANE + (r + dh) * CP + cs * 16 + g + dw;
                    A[t2][0] = s_hi[base];             A[t2][1] = s_hi[base + 8];
                    A[t2][2] = s_hi[base + 4 * PLANE]; A[t2][3] = s_hi[base + 8 + 4 * PLANE];
                    A[t2][4] = s_lo[base];             A[t2][5] = s_lo[base + 8];
                    A[t2][6] = s_lo[base + 4 * PLANE]; A[t2][7] = s_lo[base + 8 + 4 * PLANE];
                }
#pragma unroll
                for (int c4 = 0; c4 < 4; c4++) {
                    const int ct = half * 4 + c4;
                    const int wb = (ct * 8 + g) * 72 + tap;
                    unsigned bh0 = s_wh[wb + t * 9], bh1 = s_wh[wb + (t + 4) * 9];
                    unsigned bl0 = s_wl[wb + t * 9], bl1 = s_wl[wb + (t + 4) * 9];
#pragma unroll
                    for (int t2 = 0; t2 < 2; t2++) {
                        mma_tf32(acc[c4][t2][0], acc[c4][t2][1], acc[c4][t2][2], acc[c4][t2][3],
                                 A[t2][0], A[t2][1], A[t2][2], A[t2][3], bh0, bh1);
                        mma_tf32(acc[c4][t2][0], acc[c4][t2][1], acc[c4][t2][2], acc[c4][t2][3],
                                 A[t2][0], A[t2][1], A[t2][2], A[t2][3], bl0, bl1);
                        mma_tf32(acc[c4][t2][0], acc[c4][t2][1], acc[c4][t2][2], acc[c4][t2][3],
                                 A[t2][4], A[t2][5], A[t2][6], A[t2][7], bh0, bh1);
                    }
                }
            }
        }

#pragma unroll
        for (int c4 = 0; c4 < 4; c4++) {
#pragma unroll
            for (int t2 = 0; t2 < 2; t2++) {
                const int id = warp + 8 * t2;
                const int r = id >> 2, cs = id & 3;
                const int h = h0 + r, w = w0 + cs * 16 + g;
                const int co = (half * 4 + c4) * 8 + 2 * t;
                const int ob = ((n * 64 + co) * HW + h) * HW + w;
                out[ob]               = acc[c4][t2][0];
                out[ob + HW * HW]     = acc[c4][t2][1];
                out[ob + 8]           = acc[c4][t2][2];
                out[ob + HW * HW + 8] = acc[c4][t2][3];
            }
        }
    }
}

// ---------------------------------------------------------------------------
extern "C" void kernel_launch(void* const* d_in, const int* in_sizes, int n_in,
                              void* d_out, int out_size)
{
    const float* x     = (const float*)d_in[0];
    const float* p1_w1 = (const float*)d_in[1];
    const float* p1_b1 = (const float*)d_in[2];
    const float* p1_w2 = (const float*)d_in[3];
    const float* p1_b2 = (const float*)d_in[4];
    const float* gw_w1 = (const float*)d_in[5];
    const float* gw_b1 = (const float*)d_in[6];
    const float* gw_w2 = (const float*)d_in[7];
    const float* gw_b2 = (const float*)d_in[8];
    const float* p2_w1 = (const float*)d_in[9];
    const float* p2_b1 = (const float*)d_in[10];
    const float* p2_w2 = (const float*)d_in[11];
    const float* p2_b2 = (const float*)d_in[12];
    float* out = (float*)d_out;

    float *t1, *gg, *xp, *wts, *up, *mid;
    cudaGetSymbolAddress((void**)&t1,  g_t1);
    cudaGetSymbolAddress((void**)&gg,  g_g);
    cudaGetSymbolAddress((void**)&xp,  g_xp);
    cudaGetSymbolAddress((void**)&wts, g_wts);
    cudaGetSymbolAddress((void**)&up,  g_up);
    cudaGetSymbolAddress((void**)&mid, g_mid);

    const int SMEM_S1  = (8 * 408 * 2) * 4 + 2304 * 2 * 4;                  // 44544 B
    const int SMEM_P1B = (8 * 408 * 2) * 4 + 1152 * 2 * 4;                  // 35328 B
    const int SMEM_A   = (16 * 552 * 2) * 4 + 3200 * 2 * 4 + 8 * 4;         // 96288 B
    const int SMEM_B   = (8 * 408 * 2) * 4 + 4608 * 2 * 4 + 64 * 4;         // 63232 B
    cudaFuncSetAttribute(conv_s1_mma,  cudaFuncAttributeMaxDynamicSharedMemorySize, SMEM_S1);
    cudaFuncSetAttribute(conv_k3_mma<32, 16, true>,
                         cudaFuncAttributeMaxDynamicSharedMemorySize, SMEM_P1B);
    cudaFuncSetAttribute(conv_p2a_mma, cudaFuncAttributeMaxDynamicSharedMemorySize, SMEM_A);
    cudaFuncSetAttribute(conv_p2b_mma, cudaFuncAttributeMaxDynamicSharedMemorySize, SMEM_B);

    // stage 1: dual 64->32 k3 ReLU on tensor cores
    conv_s1_mma<<<dim3(2, 32, 16), 256, SMEM_S1>>>(x, p1_w1, p1_b1, t1,
                                                   gw_w1, gw_b1, gg);
    // project1 conv2 (32->16, k3, ReLU) on tensor cores
    conv_k3_mma<32, 16, true><<<dim3(2, 32, 8), 256, SMEM_P1B>>>(t1, p1_w2, p1_b2, xp);
    gw_softmax_kernel<<<512, 256>>>(gg, gw_w2, gw_b2, wts);
    upsample_kernel<<<dim3(8, 128, 8), dim3(64, 4)>>>(xp, wts, up);

    // project2 on tensor cores (tf32 x3)
    conv_p2a_mma<<<dim3(8, 128, 8), 256, SMEM_A>>>(up, p2_w1, p2_b1, mid);
    conv_p2b_mma<<<dim3(8, 128, 8), 256, SMEM_B>>>(mid, p2_w2, p2_b2, out);
}

// round 13
// speedup vs baseline: 1.4772x; 1.4772x over previous
#include <cuda_runtime.h>

// ---------------- scratch (device globals; no allocations allowed) ----------
__device__ float g_t1 [8 * 32 * 128 * 128];      // project1 conv1 out (ReLU)
__device__ float g_g  [8 * 32 * 128 * 128];      // guidance conv1 out (ReLU)
__device__ float g_xp [8 * 16 * 128 * 128];      // project1 conv2 out (ReLU)
__device__ float g_wts[8 * 16 * 9 * 128 * 128];  // softmax weights (n, pq, k, hw)
__device__ float g_up [8 * 16 * 512 * 512];      // upsampled NCHW
__device__ float g_mid[8 *  8 * 512 * 512];      // project2 conv1 out (ReLU)

// ---------------- tf32 helpers ----------------------------------------------
__device__ __forceinline__ unsigned tf32_rna(float x) {
    unsigned r; asm("cvt.rna.tf32.f32 %0, %1;" : "=r"(r) : "f"(x)); return r;
}
__device__ __forceinline__ void mma_tf32(float& c0, float& c1, float& c2, float& c3,
                                         unsigned a0, unsigned a1, unsigned a2, unsigned a3,
                                         unsigned b0, unsigned b1) {
    asm volatile("mma.sync.aligned.m16n8k8.row.col.f32.tf32.tf32.f32 "
                 "{%0,%1,%2,%3}, {%4,%5,%6,%7}, {%8,%9}, {%0,%1,%2,%3};"
                 : "+f"(c0), "+f"(c1), "+f"(c2), "+f"(c3)
                 : "r"(a0), "r"(a1), "r"(a2), "r"(a3), "r"(b0), "r"(b1));
}

// ============ generic k3 conv via tf32 MMA on 128x128 images =================
// Tile: 4 rows x 64 cols. CIN processed in CIN/8 chunks of 8.
// CT = COUT/8 output-channel groups. Weights pre-split tf32 hi/lo in smem.
template <int CIN, int COUT, bool RELU>
__global__ __launch_bounds__(256)
void conv_k3_mma(const float* __restrict__ in,
                 const float* __restrict__ wgt,
                 const float* __restrict__ bias,
                 float* __restrict__ out)
{
    constexpr int HW = 128;
    constexpr int CP = 68;
    constexpr int PLANE = 6 * CP;
    constexpr int NCH = CIN / 8;
    constexpr int CT  = COUT / 8;
    constexpr int WSZ = COUT * 8 * 9;      // weights per cin-chunk
    extern __shared__ unsigned sm[];
    unsigned* s_hi = sm;                   // [8][6][CP]
    unsigned* s_lo = s_hi + 8 * PLANE;
    unsigned* s_wh = s_lo + 8 * PLANE;     // [COUT][8 ci][9 tap]
    unsigned* s_wl = s_wh + WSZ;

    const int n  = blockIdx.z;
    const int h0 = blockIdx.y * 4;
    const int w0 = blockIdx.x * 64;
    const int tid = threadIdx.x;
    const int warp = tid >> 5, lane = tid & 31;
    const int g = lane >> 2, t = lane & 3;

    float acc[CT][2][4];
#pragma unroll
    for (int ct = 0; ct < CT; ct++) {
        float b0 = bias[ct * 8 + 2 * t], b1 = bias[ct * 8 + 2 * t + 1];
#pragma unroll
        for (int t2 = 0; t2 < 2; t2++) {
            acc[ct][t2][0] = b0; acc[ct][t2][1] = b1;
            acc[ct][t2][2] = b0; acc[ct][t2][3] = b1;
        }
    }

#pragma unroll 1
    for (int chunk = 0; chunk < NCH; chunk++) {
        __syncthreads();
        for (int i = tid; i < 8 * 6 * 66; i += 256) {
            int ci = i / 396, rem = i % 396;
            int r = rem / 66, c = rem % 66;
            int gh = h0 + r - 1, gw = w0 + c - 1;
            float v = 0.f;
            if (gh >= 0 && gh < HW && gw >= 0 && gw < HW)
                v = in[((n * CIN + chunk * 8 + ci) * HW + gh) * HW + gw];
            unsigned hi = tf32_rna(v);
            int a = ci * PLANE + r * CP + c;
            s_hi[a] = hi;
            s_lo[a] = tf32_rna(v - __uint_as_float(hi));
        }
        for (int i = tid; i < WSZ; i += 256) {
            int co = i / 72, rem = i % 72;
            float raw = wgt[co * (CIN * 9) + chunk * 72 + rem];
            unsigned hi = tf32_rna(raw);
            s_wh[i] = hi;
            s_wl[i] = tf32_rna(raw - __uint_as_float(hi));
        }
        __syncthreads();

#pragma unroll
        for (int dh = 0; dh < 3; dh++) {
#pragma unroll
            for (int dw = 0; dw < 3; dw++) {
                const int tap = dh * 3 + dw;
                unsigned A[2][8];
#pragma unroll
                for (int t2 = 0; t2 < 2; t2++) {
                    const int id = warp + 8 * t2;
                    const int r = id >> 2, cs = id & 3;
                    const int base = t * PLANE + (r + dh) * CP + cs * 16 + g + dw;
                    A[t2][0] = s_hi[base];             A[t2][1] = s_hi[base + 8];
                    A[t2][2] = s_hi[base + 4 * PLANE]; A[t2][3] = s_hi[base + 8 + 4 * PLANE];
                    A[t2][4] = s_lo[base];             A[t2][5] = s_lo[base + 8];
                    A[t2][6] = s_lo[base + 4 * PLANE]; A[t2][7] = s_lo[base + 8 + 4 * PLANE];
                }
#pragma unroll
                for (int ct = 0; ct < CT; ct++) {
                    const int wb = (ct * 8 + g) * 72 + tap;
                    unsigned bh0 = s_wh[wb + t * 9], bh1 = s_wh[wb + (t + 4) * 9];
                    unsigned bl0 = s_wl[wb + t * 9], bl1 = s_wl[wb + (t + 4) * 9];
#pragma unroll
                    for (int t2 = 0; t2 < 2; t2++) {
                        mma_tf32(acc[ct][t2][0], acc[ct][t2][1], acc[ct][t2][2], acc[ct][t2][3],
                                 A[t2][0], A[t2][1], A[t2][2], A[t2][3], bh0, bh1);
                        mma_tf32(acc[ct][t2][0], acc[ct][t2][1], acc[ct][t2][2], acc[ct][t2][3],
                                 A[t2][0], A[t2][1], A[t2][2], A[t2][3], bl0, bl1);
                        mma_tf32(acc[ct][t2][0], acc[ct][t2][1], acc[ct][t2][2], acc[ct][t2][3],
                                 A[t2][4], A[t2][5], A[t2][6], A[t2][7], bh0, bh1);
                    }
                }
            }
        }
    }

#pragma unroll
    for (int ct = 0; ct < CT; ct++) {
#pragma unroll
        for (int t2 = 0; t2 < 2; t2++) {
            const int id = warp + 8 * t2;
            const int r = id >> 2, cs = id & 3;
            const int h = h0 + r, w = w0 + cs * 16 + g;
            const int co = ct * 8 + 2 * t;
            const int ob = ((n * COUT + co) * HW + h) * HW + w;
            float v0 = acc[ct][t2][0], v1 = acc[ct][t2][1];
            float v2 = acc[ct][t2][2], v3 = acc[ct][t2][3];
            if (RELU) { v0 = fmaxf(v0, 0.f); v1 = fmaxf(v1, 0.f);
                        v2 = fmaxf(v2, 0.f); v3 = fmaxf(v3, 0.f); }
            out[ob]               = v0;
            out[ob + HW * HW]     = v1;
            out[ob + 8]           = v2;
            out[ob + HW * HW + 8] = v3;
        }
    }
}

// ============ stage-1 dual 64->32 k3 ReLU via tf32 MMA (128x128) =============
__global__ __launch_bounds__(256)
void conv_s1_mma(const float* __restrict__ in,
                 const float* __restrict__ wA, const float* __restrict__ bA,
                 float* __restrict__ outA,
                 const float* __restrict__ wB, const float* __restrict__ bB,
                 float* __restrict__ outB)
{
    constexpr int HW = 128;
    constexpr int CP = 68;
    constexpr int PLANE = 6 * CP;
    extern __shared__ unsigned sm[];
    unsigned* s_hi = sm;                   // [8][6][CP]
    unsigned* s_lo = s_hi + 8 * PLANE;
    unsigned* s_wh = s_lo + 8 * PLANE;     // [32 co][8 ci][9 tap]
    unsigned* s_wl = s_wh + 2304;

    const int which = blockIdx.z & 1;
    const int n  = blockIdx.z >> 1;
    const float* wgt  = which ? wB : wA;
    const float* bias = which ? bB : bA;
    float*       out  = which ? outB : outA;

    const int h0 = blockIdx.y * 4;
    const int w0 = blockIdx.x * 64;
    const int tid = threadIdx.x;
    const int warp = tid >> 5, lane = tid & 31;
    const int g = lane >> 2, t = lane & 3;

    float acc[4][2][4];
#pragma unroll
    for (int ct = 0; ct < 4; ct++) {
        float b0 = bias[ct * 8 + 2 * t], b1 = bias[ct * 8 + 2 * t + 1];
#pragma unroll
        for (int t2 = 0; t2 < 2; t2++) {
            acc[ct][t2][0] = b0; acc[ct][t2][1] = b1;
            acc[ct][t2][2] = b0; acc[ct][t2][3] = b1;
        }
    }

#pragma unroll 1
    for (int chunk = 0; chunk < 8; chunk++) {
        __syncthreads();
        for (int i = tid; i < 8 * 6 * 66; i += 256) {
            int ci = i / 396, rem = i % 396;
            int r = rem / 66, c = rem % 66;
            int gh = h0 + r - 1, gw = w0 + c - 1;
            float v = 0.f;
            if (gh >= 0 && gh < HW && gw >= 0 && gw < HW)
                v = in[((n * 64 + chunk * 8 + ci) * HW + gh) * HW + gw];
            unsigned hi = tf32_rna(v);
            int a = ci * PLANE + r * CP + c;
            s_hi[a] = hi;
            s_lo[a] = tf32_rna(v - __uint_as_float(hi));
        }
        for (int i = tid; i < 2304; i += 256) {
            int co = i / 72, rem = i % 72;
            float raw = wgt[co * 576 + chunk * 72 + rem];
            unsigned hi = tf32_rna(raw);
            s_wh[i] = hi;
            s_wl[i] = tf32_rna(raw - __uint_as_float(hi));
        }
        __syncthreads();

#pragma unroll
        for (int dh = 0; dh < 3; dh++) {
#pragma unroll
            for (int dw = 0; dw < 3; dw++) {
                const int tap = dh * 3 + dw;
                unsigned A[2][8];
#pragma unroll
                for (int t2 = 0; t2 < 2; t2++) {
                    const int id = warp + 8 * t2;
                    const int r = id >> 2, cs = id & 3;
                    const int base = t * PLANE + (r + dh) * CP + cs * 16 + g + dw;
                    A[t2][0] = s_hi[base];             A[t2][1] = s_hi[base + 8];
                    A[t2][2] = s_hi[base + 4 * PLANE]; A[t2][3] = s_hi[base + 8 + 4 * PLANE];
                    A[t2][4] = s_lo[base];             A[t2][5] = s_lo[base + 8];
                    A[t2][6] = s_lo[base + 4 * PLANE]; A[t2][7] = s_lo[base + 8 + 4 * PLANE];
                }
#pragma unroll
                for (int ct = 0; ct < 4; ct++) {
                    const int wb = (ct * 8 + g) * 72 + tap;
                    unsigned bh0 = s_wh[wb + t * 9], bh1 = s_wh[wb + (t + 4) * 9];
                    unsigned bl0 = s_wl[wb + t * 9], bl1 = s_wl[wb + (t + 4) * 9];
#pragma unroll
                    for (int t2 = 0; t2 < 2; t2++) {
                        mma_tf32(acc[ct][t2][0], acc[ct][t2][1], acc[ct][t2][2], acc[ct][t2][3],
                                 A[t2][0], A[t2][1], A[t2][2], A[t2][3], bh0, bh1);
                        mma_tf32(acc[ct][t2][0], acc[ct][t2][1], acc[ct][t2][2], acc[ct][t2][3],
                                 A[t2][0], A[t2][1], A[t2][2], A[t2][3], bl0, bl1);
                        mma_tf32(acc[ct][t2][0], acc[ct][t2][1], acc[ct][t2][2], acc[ct][t2][3],
                                 A[t2][4], A[t2][5], A[t2][6], A[t2][7], bh0, bh1);
                    }
                }
            }
        }
    }

#pragma unroll
    for (int ct = 0; ct < 4; ct++) {
#pragma unroll
        for (int t2 = 0; t2 < 2; t2++) {
            const int id = warp + 8 * t2;
            const int r = id >> 2, cs = id & 3;
            const int h = h0 + r, w = w0 + cs * 16 + g;
            const int co = ct * 8 + 2 * t;
            const int ob = ((n * 32 + co) * HW + h) * HW + w;
            out[ob]               = fmaxf(acc[ct][t2][0], 0.f);
            out[ob + HW * HW]     = fmaxf(acc[ct][t2][1], 0.f);
            out[ob + 8]           = fmaxf(acc[ct][t2][2], 0.f);
            out[ob + HW * HW + 8] = fmaxf(acc[ct][t2][3], 0.f);
        }
    }
}

// ------------- guidance 1x1 conv (32->144) + per-(p,q) softmax over 9 -------
__global__ void gw_softmax_kernel(const float* __restrict__ g,
                                  const float* __restrict__ w2,
                                  const float* __restrict__ b2,
                                  float* __restrict__ wts)
{
    constexpr int HW = 128 * 128;
    __shared__ float s_w[144 * 32];
    __shared__ float s_b[144];
    for (int i = threadIdx.x; i < 144 * 32; i += 256) s_w[i] = w2[i];
    for (int i = threadIdx.x; i < 144;      i += 256) s_b[i] = b2[i];
    __syncthreads();

    const int pix = blockIdx.x * 256 + threadIdx.x;
    const int n = pix / HW, hw = pix % HW;

    float gv[32];
#pragma unroll
    for (int c = 0; c < 32; c++) gv[c] = g[(n * 32 + c) * HW + hw];

    for (int pq = 0; pq < 16; pq++) {
        float v[9];
#pragma unroll
        for (int k = 0; k < 9; k++) {
            const int ch = k * 16 + pq;
            float acc = s_b[ch];
            const float* wp = &s_w[ch * 32];
#pragma unroll
            for (int c = 0; c < 32; c++) acc = fmaf(gv[c], wp[c], acc);
            v[k] = acc;
        }
        float m = v[0];
#pragma unroll
        for (int k = 1; k < 9; k++) m = fmaxf(m, v[k]);
        float s = 0.f;
#pragma unroll
        for (int k = 0; k < 9; k++) { v[k] = __expf(v[k] - m); s += v[k]; }
        const float inv = 1.f / s;
#pragma unroll
        for (int k = 0; k < 9; k++)
            wts[((n * 16 + pq) * 9 + k) * HW + hw] = v[k] * inv;
    }
}

// ------------- convex upsample + pixel shuffle ------------------------------
__global__ void upsample_kernel(const float* __restrict__ xp,
                                const float* __restrict__ wts,
                                float* __restrict__ up)
{
    constexpr int H = 128, W = 128, HW = H * W;
    __shared__ float s_xp[16][3][18];

    const int n = blockIdx.z, h = blockIdx.y, wtile = blockIdx.x * 16;
    const int tid = threadIdx.y * 64 + threadIdx.x;

    for (int i = tid; i < 16 * 3 * 18; i += 256) {
        int c = i / 54, rem = i % 54, r = rem / 18, col = rem % 18;
        int gh = h + r - 1, gw = wtile + col - 1;
        float v = 0.f;
        if (gh >= 0 && gh < H && gw >= 0 && gw < W)
            v = xp[(n * 16 + c) * HW + gh * W + gw];
        s_xp[c][r][col] = v;
    }
    __syncthreads();

    const int p  = threadIdx.y;
    const int q  = threadIdx.x & 3;
    const int wl = threadIdx.x >> 2;
    const int pq = p * 4 + q;
    const int hw = h * W + wtile + wl;

    float wt[9];
#pragma unroll
    for (int k = 0; k < 9; k++) wt[k] = wts[((n * 16 + pq) * 9 + k) * HW + hw];

    const int h_hi = h * 4 + p;
    const int w_hi = (wtile + wl) * 4 + q;
#pragma unroll
    for (int c = 0; c < 16; c++) {
        float acc = 0.f;
#pragma unroll
        for (int i = 0; i < 3; i++)
#pragma unroll
            for (int j = 0; j < 3; j++)
                acc = fmaf(wt[i * 3 + j], s_xp[c][i][wl + j], acc);
        up[((n * 16 + c) * 512 + h_hi) * 512 + w_hi] = acc;
    }
}

// ================= project2 conv1: 16->8, k5, ReLU, 512x512, tf32 MMA ========
__global__ __launch_bounds__(256)
void conv_p2a_mma(const float* __restrict__ in,
                  const float* __restrict__ wgt,
                  const float* __restrict__ bias,
                  float* __restrict__ out)
{
    constexpr int HW = 512;
    constexpr int CP = 69;
    constexpr int PLANE = 8 * CP;
    extern __shared__ unsigned sm[];
    unsigned* s_hi = sm;                    // 16*PLANE
    unsigned* s_lo = s_hi + 16 * PLANE;
    unsigned* s_wh = s_lo + 16 * PLANE;     // 3200
    unsigned* s_wl = s_wh + 3200;           // 3200
    float*    s_b  = (float*)(s_wl + 3200);

    const int n  = blockIdx.z;
    const int h0 = blockIdx.y * 4;
    const int w0 = blockIdx.x * 64;
    const int tid = threadIdx.x;

    for (int i = tid; i < 16 * 8 * 68; i += 256) {
        int cin = i / (8 * 68), rem = i % (8 * 68);
        int r = rem / 68, c = rem % 68;
        int gh = h0 + r - 2, gw = w0 + c - 2;
        float v = 0.f;
        if (gh >= 0 && gh < HW && gw >= 0 && gw < HW)
            v = in[((n * 16 + cin) * HW + gh) * HW + gw];
        unsigned hi = tf32_rna(v);
        float lo = v - __uint_as_float(hi);
        int a = cin * PLANE + r * CP + c;
        s_hi[a] = hi;
        s_lo[a] = tf32_rna(lo);
    }
    for (int i = tid; i < 3200; i += 256) {
        float raw = wgt[i];
        unsigned hi = tf32_rna(raw);
        s_wh[i] = hi;
        s_wl[i] = tf32_rna(raw - __uint_as_float(hi));
    }
    if (tid < 8) s_b[tid] = bias[tid];
    __syncthreads();

    const int warp = tid >> 5, lane = tid & 31;
    const int g = lane >> 2, t = lane & 3;

    float c[2][4];
#pragma unroll
    for (int t2 = 0; t2 < 2; t2++) {
        c[t2][0] = s_b[2 * t];     c[t2][1] = s_b[2 * t + 1];
        c[t2][2] = c[t2][0];       c[t2][3] = c[t2][1];
    }

#pragma unroll
    for (int dh = 0; dh < 5; dh++) {
#pragma unroll
        for (int dw = 0; dw < 5; dw++) {
            const int tap = dh * 5 + dw;
#pragma unroll
            for (int ch = 0; ch < 2; ch++) {
                const int wb0 = g * 400 + (ch * 8 + t) * 25 + tap;
                const int wb1 = g * 400 + (ch * 8 + t + 4) * 25 + tap;
                unsigned bh0 = s_wh[wb0], bh1 = s_wh[wb1];
                unsigned bl0 = s_wl[wb0], bl1 = s_wl[wb1];
#pragma unroll
                for (int t2 = 0; t2 < 2; t2++) {
                    const int id = warp + 8 * t2;
                    const int r = id >> 2, cs = id & 3;
                    const int base = (ch * 8 + t) * PLANE + (r + dh) * CP + cs * 16 + g + dw;
                    unsigned a0 = s_hi[base],             a1 = s_hi[base + 8];
                    unsigned a2 = s_hi[base + 4 * PLANE], a3 = s_hi[base + 4 * PLANE + 8];
                    unsigned l0 = s_lo[base],             l1 = s_lo[base + 8];
                    unsigned l2 = s_lo[base + 4 * PLANE], l3 = s_lo[base + 4 * PLANE + 8];
                    mma_tf32(c[t2][0], c[t2][1], c[t2][2], c[t2][3], a0, a1, a2, a3, bh0, bh1);
                    mma_tf32(c[t2][0], c[t2][1], c[t2][2], c[t2][3], a0, a1, a2, a3, bl0, bl1);
                    mma_tf32(c[t2][0], c[t2][1], c[t2][2], c[t2][3], l0, l1, l2, l3, bh0, bh1);
                }
            }
        }
    }

#pragma unroll
    for (int t2 = 0; t2 < 2; t2++) {
        const int id = warp + 8 * t2;
        const int r = id >> 2, cs = id & 3;
        const int h = h0 + r, w = w0 + cs * 16 + g;
        const int ob = ((n * 8 + 2 * t) * HW + h) * HW + w;
        out[ob]                = fmaxf(c[t2][0], 0.f);
        out[ob + HW * HW]      = fmaxf(c[t2][1], 0.f);
        out[ob + 8]            = fmaxf(c[t2][2], 0.f);
        out[ob + HW * HW + 8]  = fmaxf(c[t2][3], 0.f);
    }
}

// ================= project2 conv2: 8->64, k3, 512x512, tf32 MMA ==============
__global__ __launch_bounds__(256)
void conv_p2b_mma(const float* __restrict__ in,
                  const float* __restrict__ wgt,
                  const float* __restrict__ bias,
                  float* __restrict__ out)
{
    constexpr int HW = 512;
    constexpr int CP = 68;
    constexpr int PLANE = 6 * CP;
    extern __shared__ unsigned sm[];
    unsigned* s_hi = sm;                    // 8*PLANE
    unsigned* s_lo = s_hi + 8 * PLANE;
    unsigned* s_wh = s_lo + 8 * PLANE;      // 4608
    unsigned* s_wl = s_wh + 4608;           // 4608
    float*    s_b  = (float*)(s_wl + 4608); // 64

    const int n  = blockIdx.z;
    const int h0 = blockIdx.y * 4;
    const int w0 = blockIdx.x * 64;
    const int tid = threadIdx.x;

    for (int i = tid; i < 8 * 6 * 66; i += 256) {
        int cin = i / (6 * 66), rem = i % (6 * 66);
        int r = rem / 66, c = rem % 66;
        int gh = h0 + r - 1, gw = w0 + c - 1;
        float v = 0.f;
        if (gh >= 0 && gh < HW && gw >= 0 && gw < HW)
            v = in[((n * 8 + cin) * HW + gh) * HW + gw];
        unsigned hi = tf32_rna(v);
        float lo = v - __uint_as_float(hi);
        int a = cin * PLANE + r * CP + c;
        s_hi[a] = hi;
        s_lo[a] = tf32_rna(lo);
    }
    for (int i = tid; i < 4608; i += 256) {
        float raw = wgt[i];
        unsigned hi = tf32_rna(raw);
        s_wh[i] = hi;
        s_wl[i] = tf32_rna(raw - __uint_as_float(hi));
    }
    if (tid < 64) s_b[tid] = bias[tid];
    __syncthreads();

    const int warp = tid >> 5, lane = tid & 31;
    const int g = lane >> 2, t = lane & 3;

#pragma unroll 1
    for (int half = 0; half < 2; half++) {
        float acc[4][2][4];
#pragma unroll
        for (int c4 = 0; c4 < 4; c4++) {
            const int ct = half * 4 + c4;
            float b0 = s_b[ct * 8 + 2 * t], b1 = s_b[ct * 8 + 2 * t + 1];
#pragma unroll
            for (int t2 = 0; t2 < 2; t2++) {
                acc[c4][t2][0] = b0; acc[c4][t2][1] = b1;
                acc[c4][t2][2] = b0; acc[c4][t2][3] = b1;
            }
        }

#pragma unroll
        for (int dh = 0; dh < 3; dh++) {
#pragma unroll
            for (int dw = 0; dw < 3; dw++) {
                const int tap = dh * 3 + dw;
                unsigned A[2][8];
#pragma unroll
                for (int t2 = 0; t2 < 2; t2++) {
                    const int id = warp + 8 * t2;
                    const int r = id >> 2, cs = id & 3;
                    const int base = t * PLANE + (r + dh) * CP + cs * 16 + g + dw;
                    A[t2][0] = s_hi[base];             A[t2][1] = s_hi[base + 8];
                    A[t2][2] = s_hi[base + 4 * PLANE]; A[t2][3] = s_hi[base + 8 + 4 * PLANE];
                    A[t2][4] = s_lo[base];             A[t2][5] = s_lo[base + 8];
                    A[t2][6] = s_lo[base + 4 * PLANE]; A[t2][7] = s_lo[base + 8 + 4 * PLANE];
                }
#pragma unroll
                for (int c4 = 0; c4 < 4; c4++) {
                    const int ct = half * 4 + c4;
                    const int wb = (ct * 8 + g) * 72 + tap;
                    unsigned bh0 = s_wh[wb + t * 9], bh1 = s_wh[wb + (t + 4) * 9];
                    unsigned bl0 = s_wl[wb + t * 9], bl1 = s_wl[wb + (t + 4) * 9];
#pragma unroll
                    for (int t2 = 0; t2 < 2; t2++) {
                        mma_tf32(acc[c4][t2][0], acc[c4][t2][1], acc[c4][t2][2], acc[c4][t2][3],
                                 A[t2][0], A[t2][1], A[t2][2], A[t2][3], bh0, bh1);
                        mma_tf32(acc[c4][t2][0], acc[c4][t2][1], acc[c4][t2][2], acc[c4][t2][3],
                                 A[t2][0], A[t2][1], A[t2][2], A[t2][3], bl0, bl1);
                        mma_tf32(acc[c4][t2][0], acc[c4][t2][1], acc[c4][t2][2], acc[c4][t2][3],
                                 A[t2][4], A[t2][5], A[t2][6], A[t2][7], bh0, bh1);
                    }
                }
            }
        }

#pragma unroll
        for (int c4 = 0; c4 < 4; c4++) {
#pragma unroll
            for (int t2 = 0; t2 < 2; t2++) {
                const int id = warp + 8 * t2;
                const int r = id >> 2, cs = id & 3;
                const int h = h0 + r, w = w0 + cs * 16 + g;
                const int co = (half * 4 + c4) * 8 + 2 * t;
                const int ob = ((n * 64 + co) * HW + h) * HW + w;
                out[ob]               = acc[c4][t2][0];
                out[ob + HW * HW]     = acc[c4][t2][1];
                out[ob + 8]           = acc[c4][t2][2];
                out[ob + HW * HW + 8] = acc[c4][t2][3];
            }
        }
    }
}

// ---------------------------------------------------------------------------
extern "C" void kernel_launch(void* const* d_in, const int* in_sizes, int n_in,
                              void* d_out, int out_size)
{
    const float* x     = (const float*)d_in[0];
    const float* p1_w1 = (const float*)d_in[1];
    const float* p1_b1 = (const float*)d_in[2];
    const float* p1_w2 = (const float*)d_in[3];
    const float* p1_b2 = (const float*)d_in[4];
    const float* gw_w1 = (const float*)d_in[5];
    const float* gw_b1 = (const float*)d_in[6];
    const float* gw_w2 = (const float*)d_in[7];
    const float* gw_b2 = (const float*)d_in[8];
    const float* p2_w1 = (const float*)d_in[9];
    const float* p2_b1 = (const float*)d_in[10];
    const float* p2_w2 = (const float*)d_in[11];
    const float* p2_b2 = (const float*)d_in[12];
    float* out = (float*)d_out;

    float *t1, *gg, *xp, *wts, *up, *mid;
    cudaGetSymbolAddress((void**)&t1,  g_t1);
    cudaGetSymbolAddress((void**)&gg,  g_g);
    cudaGetSymbolAddress((void**)&xp,  g_xp);
    cudaGetSymbolAddress((void**)&wts, g_wts);
    cudaGetSymbolAddress((void**)&up,  g_up);
    cudaGetSymbolAddress((void**)&mid, g_mid);

    const int SMEM_S1  = (8 * 408 * 2) * 4 + 2304 * 2 * 4;                  // 44544 B
    const int SMEM_P1B = (8 * 408 * 2) * 4 + 1152 * 2 * 4;                  // 35328 B
    const int SMEM_A   = (16 * 552 * 2) * 4 + 3200 * 2 * 4 + 8 * 4;         // 96288 B
    const int SMEM_B   = (8 * 408 * 2) * 4 + 4608 * 2 * 4 + 64 * 4;         // 63232 B
    cudaFuncSetAttribute(conv_s1_mma,  cudaFuncAttributeMaxDynamicSharedMemorySize, SMEM_S1);
    cudaFuncSetAttribute(conv_k3_mma<32, 16, true>,
                         cudaFuncAttributeMaxDynamicSharedMemorySize, SMEM_P1B);
    cudaFuncSetAttribute(conv_p2a_mma, cudaFuncAttributeMaxDynamicSharedMemorySize, SMEM_A);
    cudaFuncSetAttribute(conv_p2b_mma, cudaFuncAttributeMaxDynamicSharedMemorySize, SMEM_B);

    // stage 1: dual 64->32 k3 ReLU on tensor cores
    conv_s1_mma<<<dim3(2, 32, 16), 256, SMEM_S1>>>(x, p1_w1, p1_b1, t1,
                                                   gw_w1, gw_b1, gg);
    // project1 conv2 (32->16, k3, ReLU) on tensor cores
    conv_k3_mma<32, 16, true><<<dim3(2, 32, 8), 256, SMEM_P1B>>>(t1, p1_w2, p1_b2, xp);
    gw_softmax_kernel<<<512, 256>>>(gg, gw_w2, gw_b2, wts);
    upsample_kernel<<<dim3(8, 128, 8), dim3(64, 4)>>>(xp, wts, up);

    // project2 on tensor cores (tf32 x3)
    conv_p2a_mma<<<dim3(8, 128, 8), 256, SMEM_A>>>(up, p2_w1, p2_b1, mid);
    conv_p2b_mma<<<dim3(8, 128, 8), 256, SMEM_B>>>(mid, p2_w2, p2_b2, out);
}